// round 16
// baseline (speedup 1.0000x reference)
#include <cuda_runtime.h>
#include <cuda_fp16.h>

// Critic_66511863546286 — folded attention critic, round 16.
// B=256, S=1024, H=256, feat dims = 2, 3 iterations.
// R16 = R15 with the v-accumulation MMA batched to m16n8k16: two h-tiles'
// tanh'd D-fragments stack in k (k16 A-frag layout == two k8 D-frags), so
// ONE full-rate f32 acc-MMA replaces two wasteful k8 acc-MMAs. Tensor
// instructions per warp-iter: 256 -> 192. Poly fraction stays 3/4.

#define NB 256
#define NS 1024
#define NH 256
#define K3 768
#define NITER 3
#define NFC 20
#define BT 512    // threads/block; thread t owns points t (lo) and t+512 (hi)

// Precomputed fused coefficients (natural scale, f32 masters).
__device__ float4 gABp[NH];  // (A0, A1, B0, B1) per h
__device__ float4 gCdv[NH];  // (C0, C1, d, v[h])
__device__ float2 gF[NFC];   // fc1_w · sw
__device__ float  gfb[NFC];  // fc1_w · sb + fc1_b

__device__ __forceinline__ float ex2_approx(float x) {
    float y; asm("ex2.approx.f32 %0, %1;" : "=f"(y) : "f"(x)); return y;
}
__device__ __forceinline__ unsigned hfma2u(unsigned a, unsigned b, unsigned c) {
    unsigned d;
    asm("fma.rn.f16x2 %0, %1, %2, %3;" : "=r"(d) : "r"(a), "r"(b), "r"(c));
    return d;
}
__device__ __forceinline__ unsigned hmul2u(unsigned a, unsigned b) {
    unsigned d;
    asm("mul.rn.f16x2 %0, %1, %2;" : "=r"(d) : "r"(a), "r"(b));
    return d;
}
__device__ __forceinline__ unsigned tanh16x2(unsigned x) {
    unsigned y; asm("tanh.approx.f16x2 %0, %1;" : "=r"(y) : "r"(x)); return y;
}
__device__ __forceinline__ unsigned f2h2(float a, float b) {
    __half2 h = __floats2half2_rn(a, b);
    return *reinterpret_cast<unsigned*>(&h);
}
// D(16x8) = A(16x8) * B(8x8) + C ; all f16. A: 2 regs, B: 1, C/D: 2.
__device__ __forceinline__ void mma16n8k8(unsigned& d0, unsigned& d1,
    unsigned a0, unsigned a1, unsigned b0, unsigned c0, unsigned c1) {
    asm("mma.sync.aligned.m16n8k8.row.col.f16.f16.f16.f16 "
        "{%0,%1}, {%2,%3}, {%4}, {%5,%6};"
        : "=r"(d0), "=r"(d1)
        : "r"(a0), "r"(a1), "r"(b0), "r"(c0), "r"(c1));
}
// D(16x8,f32) += A(16x16,f16) * B(16x8,f16). A: 4 regs, B: 2, C/D: 4 f32.
__device__ __forceinline__ void mma16n8k16_f32(float* c,
    unsigned a0, unsigned a1, unsigned a2, unsigned a3,
    unsigned b0, unsigned b1) {
    asm("mma.sync.aligned.m16n8k16.row.col.f32.f16.f16.f32 "
        "{%0,%1,%2,%3}, {%4,%5,%6,%7}, {%8,%9}, {%0,%1,%2,%3};"
        : "+f"(c[0]), "+f"(c[1]), "+f"(c[2]), "+f"(c[3])
        : "r"(a0), "r"(a1), "r"(a2), "r"(a3), "r"(b0), "r"(b1));
}

// ---------------------------------------------------------------------------
// Precompute: fold W through the 1x1-conv encoders (f32 masters).
// ---------------------------------------------------------------------------
__global__ void precompute_kernel(
    const float* __restrict__ sw, const float* __restrict__ sb,
    const float* __restrict__ dw, const float* __restrict__ db,
    const float* __restrict__ W,  const float* __restrict__ v,
    const float* __restrict__ fc1_w, const float* __restrict__ fc1_b)
{
    __shared__ float sred[8][8];
    int tid = threadIdx.x;
    int blk = blockIdx.x;
    int lane = tid & 31, w = tid >> 5;

    if (blk < NH) {
        int h = blk;
        float ws = W[h * K3 + tid];
        float wd = W[h * K3 + 256 + tid];
        float wc = W[h * K3 + 512 + tid];
        float s0 = sw[tid * 2 + 0], s1 = sw[tid * 2 + 1];
        float sbk = sb[tid];
        float p[7];
        p[0] = ws * s0;
        p[1] = ws * s1;
        p[2] = wd * dw[tid * 2 + 0];
        p[3] = wd * dw[tid * 2 + 1];
        p[4] = wc * s0;
        p[5] = wc * s1;
        p[6] = ws * sbk + wd * db[tid] + wc * sbk;
        #pragma unroll
        for (int o = 16; o > 0; o >>= 1)
            #pragma unroll
            for (int i = 0; i < 7; i++)
                p[i] += __shfl_xor_sync(0xffffffffu, p[i], o);
        if (lane == 0) {
            #pragma unroll
            for (int i = 0; i < 7; i++) sred[w][i] = p[i];
        }
        __syncthreads();
        if (tid == 0) {
            float q[7];
            #pragma unroll
            for (int i = 0; i < 7; i++) {
                q[i] = 0.f;
                for (int ww = 0; ww < 8; ww++) q[i] += sred[ww][i];
            }
            gABp[h] = make_float4(q[0], q[1], q[2], q[3]);
            gCdv[h] = make_float4(q[4], q[5], q[6], v[h]);
        }
    } else {
        int j = blk - NH;
        float fw = fc1_w[j * NH + tid];
        float p0 = fw * sw[tid * 2 + 0];
        float p1 = fw * sw[tid * 2 + 1];
        float p2 = fw * sb[tid];
        #pragma unroll
        for (int o = 16; o > 0; o >>= 1) {
            p0 += __shfl_xor_sync(0xffffffffu, p0, o);
            p1 += __shfl_xor_sync(0xffffffffu, p1, o);
            p2 += __shfl_xor_sync(0xffffffffu, p2, o);
        }
        if (lane == 0) { sred[w][0] = p0; sred[w][1] = p1; sred[w][2] = p2; }
        __syncthreads();
        if (tid == 0) {
            float q0 = 0.f, q1 = 0.f, q2 = 0.f;
            for (int ww = 0; ww < 8; ww++) {
                q0 += sred[ww][0]; q1 += sred[ww][1]; q2 += sred[ww][2];
            }
            gF[j] = make_float2(q0, q1);
            gfb[j] = q2 + fc1_b[j];
        }
    }
}

// ---------------------------------------------------------------------------
// Main kernel: one block per batch; 512 threads; warp w owns points
// [64w, 64w+64) for the MMA stage; thread t owns points t, t+512 for the
// softmax stage (scores passed through shared sScore).
// ---------------------------------------------------------------------------
__global__ void __launch_bounds__(BT, 2)
attn_kernel(const float* __restrict__ stat, const float* __restrict__ dyn,
            const float* __restrict__ istate,
            const float* __restrict__ fc2_w, const float* __restrict__ fc2_b,
            float* __restrict__ out)
{
    __shared__ uint2 sU[NS];         // per-point features {(x0,x1),(y0,y1)} f16
    __shared__ unsigned sBf[NH * 4]; // per-h B-frag half2s {(A0,A1),(B0,B1),0,0}
    __shared__ uint2 sGV[NH / 2];    // per h-pair {(g,g'), (v,v')} f16
    __shared__ float4 sCdv[NH];      // (C0,C1,d,v) f32
    __shared__ float sScore[NS];     // scores handoff
    __shared__ float sredM[16], sredP[16], sredX[16], sredY[16];
    __shared__ float bc[4];

    const float LOG2E = 1.4426950408889634f;
    int b = blockIdx.x;
    int s = threadIdx.x;              // 0..511
    int lane = s & 31, warp = s >> 5;
    int gid = lane >> 2, tig = lane & 3;

    // odd-quintic tanh: tanh(x) ~= x*(1 + x2*(PA + PB*x2))
    const unsigned PA2 = f2h2(-0.3248f, -0.3248f);
    const unsigned PB2 = f2h2(0.0864f, 0.0864f);
    const unsigned ONE2 = f2h2(1.0f, 1.0f);

    // features for points s (lo) and s+512 (hi); f32 masters for softmax
    float x0l = stat[b * 2 * NS + s],      x0h = stat[b * 2 * NS + s + BT];
    float x1l = stat[b * 2 * NS + NS + s], x1h = stat[b * 2 * NS + NS + s + BT];
    float y0l = dyn[b * 2 * NS + s],       y0h = dyn[b * 2 * NS + s + BT];
    float y1l = dyn[b * 2 * NS + NS + s],  y1h = dyn[b * 2 * NS + NS + s + BT];

    // shared feature table (f16) for A-fragments
    sU[s]      = make_uint2(f2h2(x0l, x1l), f2h2(y0l, y1l));
    sU[s + BT] = make_uint2(f2h2(x0h, x1h), f2h2(y0h, y1h));

    if (s < NH) {
        sCdv[s] = gCdv[s];
        float4 q = gABp[s];
        sBf[s * 4 + 0] = f2h2(q.x, q.y);   // (A0, A1)
        sBf[s * 4 + 1] = f2h2(q.z, q.w);   // (B0, B1)
        sBf[s * 4 + 2] = 0u;               // k-pad
        sBf[s * 4 + 3] = 0u;
    }
    __syncthreads();

    // A fragments: constant across iterations and h-tiles.
    // pt-tile p covers points warp*64 + p*16 + {0..15}.
    unsigned a01[4], a23[4];
    #pragma unroll
    for (int p = 0; p < 4; p++) {
        int pt0 = (warp << 6) + (p << 4) + gid;
        uint2 F0 = sU[pt0];
        uint2 F1 = sU[pt0 + 8];
        a01[p] = (tig == 0) ? F0.x : (tig == 1) ? F0.y : 0u;
        a23[p] = (tig == 0) ? F1.x : (tig == 1) ? F1.y : 0u;
    }

    float z0 = istate[b * 2 + 0];
    float z1 = istate[b * 2 + 1];

    for (int it = 0; it < NITER; it++) {
        __syncthreads();
        if (s < NH / 2) {
            float4 ca = sCdv[2 * s];
            float4 cb = sCdv[2 * s + 1];
            float ga = fmaf(ca.x, z0, fmaf(ca.y, z1, ca.z));
            float gb = fmaf(cb.x, z0, fmaf(cb.y, z1, cb.z));
            sGV[s] = make_uint2(f2h2(ga, gb), f2h2(ca.w, cb.w));
        }
        __syncthreads();

        // MMA mainloop: 16 h-tile PAIRS (2x8 h); 4 pt-tiles of 16 points.
        // ht%4==0: MUFU tanh16x2; else FMA-pipe quintic (f=3/4).
        // v-accumulation: ONE m16n8k16 f32 MMA per (ht-pair, p) — the two
        // tanh'd k8 D-frags stack directly as the k16 A-frag.
        float acc[4][4];
        #pragma unroll
        for (int p = 0; p < 4; p++)
            #pragma unroll
            for (int i = 0; i < 4; i++) acc[p][i] = 0.f;

        #pragma unroll
        for (int hp = 0; hp < 16; hp++) {
            int ht0 = 2 * hp, ht1 = 2 * hp + 1;
            unsigned bf0 = sBf[((ht0 << 3) + gid) * 4 + tig];
            unsigned bf1 = sBf[((ht1 << 3) + gid) * 4 + tig];
            uint2 gv0 = sGV[(ht0 << 2) + tig];   // {(g,g'),(v,v')} tile ht0
            uint2 gv1 = sGV[(ht1 << 2) + tig];   // tile ht1
            // acc-MMA B frags: column 0 = v of each tile's 8 h, others 0
            unsigned bacc0 = (gid == 0) ? gv0.y : 0u;   // k 0-7
            unsigned bacc1 = (gid == 0) ? gv1.y : 0u;   // k 8-15
            #pragma unroll
            for (int p = 0; p < 4; p++) {
                unsigned d0a, d1a, d0b, d1b;
                mma16n8k8(d0a, d1a, a01[p], a23[p], bf0, gv0.x, gv0.x);
                mma16n8k8(d0b, d1b, a01[p], a23[p], bf1, gv1.x, gv1.x);

                unsigned th0a, th1a, th0b, th1b;
                if ((ht0 & 3) == 0) {            // MUFU tile
                    th0a = tanh16x2(d0a);
                    th1a = tanh16x2(d1a);
                } else {                          // poly tile
                    unsigned x20 = hmul2u(d0a, d0a);
                    unsigned u0  = hfma2u(x20, PB2, PA2);
                    unsigned w0  = hfma2u(u0, x20, ONE2);
                    th0a = hmul2u(w0, d0a);
                    unsigned x21 = hmul2u(d1a, d1a);
                    unsigned u1  = hfma2u(x21, PB2, PA2);
                    unsigned w1  = hfma2u(u1, x21, ONE2);
                    th1a = hmul2u(w1, d1a);
                }
                {                                 // ht1 odd -> always poly
                    unsigned x20 = hmul2u(d0b, d0b);
                    unsigned u0  = hfma2u(x20, PB2, PA2);
                    unsigned w0  = hfma2u(u0, x20, ONE2);
                    th0b = hmul2u(w0, d0b);
                    unsigned x21 = hmul2u(d1b, d1b);
                    unsigned u1  = hfma2u(x21, PB2, PA2);
                    unsigned w1  = hfma2u(u1, x21, ONE2);
                    th1b = hmul2u(w1, d1b);
                }
                mma16n8k16_f32(acc[p], th0a, th1a, th0b, th1b, bacc0, bacc1);
            }
        }

        // scores: column 0 of the f32 accumulator, held by tig==0 threads.
        if (tig == 0) {
            #pragma unroll
            for (int p = 0; p < 4; p++) {
                int pt0 = (warp << 6) + (p << 4) + gid;
                sScore[pt0]     = acc[p][0];   // row gid,   col 0
                sScore[pt0 + 8] = acc[p][2];   // row gid+8, col 0
            }
        }
        __syncthreads();

        float t0 = sScore[s];
        float t1 = sScore[s + BT];

        // ---- R9 softmax stage (verbatim) ----
        float m = fmaxf(t0, t1);
        #pragma unroll
        for (int o = 16; o > 0; o >>= 1)
            m = fmaxf(m, __shfl_xor_sync(0xffffffffu, m, o));
        if (lane == 0) sredM[warp] = m;
        __syncthreads();
        if (s < 16) {
            float mm = sredM[s];
            #pragma unroll
            for (int o = 8; o > 0; o >>= 1)
                mm = fmaxf(mm, __shfl_xor_sync(0xffffu, mm, o));
            if (s == 0) bc[0] = mm;
        }
        __syncthreads();
        float M = bc[0];

        float p0 = ex2_approx((t0 - M) * LOG2E);
        float p1 = ex2_approx((t1 - M) * LOG2E);
        float a  = p0 + p1;
        float bx = fmaf(p0, x0l, p1 * x0h);
        float by = fmaf(p0, x1l, p1 * x1h);
        #pragma unroll
        for (int o = 16; o > 0; o >>= 1) {
            a  += __shfl_xor_sync(0xffffffffu, a,  o);
            bx += __shfl_xor_sync(0xffffffffu, bx, o);
            by += __shfl_xor_sync(0xffffffffu, by, o);
        }
        if (lane == 0) { sredP[warp] = a; sredX[warp] = bx; sredY[warp] = by; }
        __syncthreads();
        if (s < 16) {
            float aa = sredP[s], xx = sredX[s], yy = sredY[s];
            #pragma unroll
            for (int o = 8; o > 0; o >>= 1) {
                aa += __shfl_xor_sync(0xffffu, aa, o);
                xx += __shfl_xor_sync(0xffffu, xx, o);
                yy += __shfl_xor_sync(0xffffu, yy, o);
            }
            if (s == 0) { bc[1] = aa; bc[2] = xx; bc[3] = yy; }
        }
        __syncthreads();
        float inv = 1.f / bc[1];
        z0 = bc[2] * inv;   // xbar0
        z1 = bc[3] * inv;   // xbar1
    }

    // Output MLP (folded through sw), f32
    if (s == 0) {
        float o = fc2_b[0];
        #pragma unroll
        for (int j = 0; j < NFC; j++) {
            float hv = fmaf(gF[j].x, z0, fmaf(gF[j].y, z1, gfb[j]));
            hv = fmaxf(hv, 0.f);
            o = fmaf(fc2_w[j], hv, o);
        }
        out[b] = o;
    }
}

extern "C" void kernel_launch(void* const* d_in, const int* in_sizes, int n_in,
                              void* d_out, int out_size)
{
    const float* stat   = (const float*)d_in[0];   // [256, 2, 1024]
    const float* dyn    = (const float*)d_in[1];   // [256, 2, 1024]
    const float* istate = (const float*)d_in[2];   // [256, 2]
    const float* sw     = (const float*)d_in[3];   // [256, 2]
    const float* sb     = (const float*)d_in[4];   // [256]
    const float* dw     = (const float*)d_in[5];   // [256, 2]
    const float* db     = (const float*)d_in[6];   // [256]
    const float* v      = (const float*)d_in[7];   // [1, 256]
    const float* W      = (const float*)d_in[8];   // [256, 768]
    const float* fc1_w  = (const float*)d_in[9];   // [20, 256]
    const float* fc1_b  = (const float*)d_in[10];  // [20]
    const float* fc2_w  = (const float*)d_in[11];  // [1, 20]
    const float* fc2_b  = (const float*)d_in[12];  // [1]
    float* out = (float*)d_out;                    // [256, 1]

    precompute_kernel<<<NH + NFC, 256>>>(sw, sb, dw, db, W, v, fc1_w, fc1_b);
    attn_kernel<<<NB, BT>>>(stat, dyn, istate, fc2_w, fc2_b, out);
}